// round 3
// baseline (speedup 1.0000x reference)
#include <cuda_runtime.h>
#include <math.h>

#define Nn 131072
#define Bg 16
#define Cc 128
#define Kk 16
#define TILE 128
#define NTHREADS 256
#define XS_STRIDE 132
#define EPSF 1e-9f

// d_out layout (flattened return tuple): out[B,K,C], s[N,K], mu[B,K,2], losses[9]
#define OUT_POOL_OFF 0
#define S_OFF        (Bg*Kk*Cc)                 // 32768
#define MU_OFF       (S_OFF + Nn*Kk)            // 2129920
#define LOSS_OFF     (MU_OFF + Bg*Kk*2)         // 2130432

// scratch accumulators (no cudaMalloc allowed)
__device__ float g_sum_s[Bg*Kk];
__device__ float g_sum_pos[Bg*Kk*2];
__device__ float g_ent;

// ---- f32x2 packed fp32 helpers (FFMA2 only reachable via explicit PTX) ----
__device__ __forceinline__ unsigned long long pack2(float lo, float hi) {
    unsigned long long r;
    asm("mov.b64 %0, {%1, %2};" : "=l"(r) : "f"(lo), "f"(hi));
    return r;
}
__device__ __forceinline__ void fma2(unsigned long long& acc,
                                     unsigned long long a, unsigned long long b) {
    asm("fma.rn.f32x2 %0, %1, %2, %0;" : "+l"(acc) : "l"(a), "l"(b));
}
__device__ __forceinline__ float2 unpack2(unsigned long long v) {
    float2 f;
    asm("mov.b64 {%0, %1}, %2;" : "=f"(f.x), "=f"(f.y) : "l"(v));
    return f;
}

// ---------------- init ----------------
__global__ void init_kernel(float* __restrict__ out_pool) {
    int idx = blockIdx.x * blockDim.x + threadIdx.x;
    if (idx < Bg*Kk*Cc) out_pool[idx] = 0.f;
    if (blockIdx.x == 0) {
        int t = threadIdx.x;
        if (t < Bg*Kk) g_sum_s[t] = 0.f;
        for (int i = t; i < Bg*Kk*2; i += blockDim.x) g_sum_pos[i] = 0.f;
        if (t == 0) g_ent = 0.f;
    }
}

// ---------------- fused main ----------------
// smem layout (floats):
//  xs   @ 0      : TILE*XS_STRIDE (16896)
//  wh   @ 16896  : Cc*XS_STRIDE   (16896)   W1 rows, later reused as h
//  w2s  @ 33792  : Kk*Cc          (2048)
//  larr @ 35840  : TILE*17        (2176)
//  ss   @ 38016  : TILE*17        (2176)
//  psm  @ 40192  : TILE*2         (256)
//  b1s  @ 40448  : 128
//  b2s  @ 40576  : 16
//  msk  @ 40592  : 16
//  bval @ 40608  : 128 (int)
//  ent  @ 40736  : 1
#define SMEM_FLOATS 40960
#define SMEM_BYTES  (SMEM_FLOATS * 4)

extern "C" __global__ void __launch_bounds__(NTHREADS, 1)
fused_kernel(const float* __restrict__ x,
             const int* __restrict__ batch,
             const float* __restrict__ pos,
             const float* __restrict__ gumbel,
             const float* __restrict__ W1,
             const float* __restrict__ b1,
             const float* __restrict__ W2,
             const float* __restrict__ b2,
             const float* __restrict__ scaling_p,
             const float* __restrict__ amask,
             float* __restrict__ out_pool,
             float* __restrict__ s_out)
{
    extern __shared__ float sm[];
    float* xs   = sm;
    float* wh   = sm + 16896;
    float* w2s  = sm + 33792;
    float* larr = sm + 35840;
    float* ss   = sm + 38016;
    float* psm  = sm + 40192;
    float* b1s  = sm + 40448;
    float* b2s  = sm + 40576;
    float* msk  = sm + 40592;
    int*   bval = (int*)(sm + 40608);
    float* entacc = sm + 40736;

    const int tid  = threadIdx.x;
    const int base = blockIdx.x * TILE;
    const int warp = tid >> 5, lane = tid & 31;
    const float sc = __ldg(scaling_p);

    // ---- cooperative loads (coalesced float4) ----
    for (int r = warp; r < TILE; r += 8) {
        float4 v = ((const float4*)(x + (size_t)(base + r) * Cc))[lane];
        *(float4*)(xs + r * XS_STRIDE + lane * 4) = v;
    }
    for (int r = warp; r < Cc; r += 8) {
        float4 v = ((const float4*)(W1 + (size_t)r * Cc))[lane];
        *(float4*)(wh + r * XS_STRIDE + lane * 4) = v;
    }
    for (int r = warp; r < Kk; r += 8) {
        float4 v = ((const float4*)(W2 + (size_t)r * Cc))[lane];
        *(float4*)(w2s + r * Cc + lane * 4) = v;
    }
    if (tid < Cc) b1s[tid] = b1[tid];
    if (tid < Kk) { b2s[tid] = b2[tid]; msk[tid] = amask[tid]; }
    if (tid < TILE) {
        int bv = batch[base + tid];          // int32 (JAX x64 disabled)
        bval[tid] = bv < 0 ? 0 : (bv >= Bg ? Bg - 1 : bv);
        psm[tid*2]   = pos[(size_t)(base + tid)*2];
        psm[tid*2+1] = pos[(size_t)(base + tid)*2 + 1];
    }
    if (tid == 0) entacc[0] = 0.f;
    __syncthreads();

    // ---- GEMM1: h[128][128], 8x8 per thread, FFMA2 (f32x2), float4 k-loads ----
    // rows m = ty + 16*i, cols n = tx + 16*j; j-pairs (2jp, 2jp+1)
    const int tx = tid & 15, ty = tid >> 4;
    unsigned long long h2[8][4];
    #pragma unroll
    for (int i = 0; i < 8; i++)
        #pragma unroll
        for (int jp = 0; jp < 4; jp++) h2[i][jp] = 0ull;

    #pragma unroll 1
    for (int k = 0; k < Cc; k += 4) {
        float4 a4[8], b4[8];
        #pragma unroll
        for (int i = 0; i < 8; i++)
            a4[i] = *(const float4*)(xs + (ty + 16*i) * XS_STRIDE + k);
        #pragma unroll
        for (int j = 0; j < 8; j++)
            b4[j] = *(const float4*)(wh + (tx + 16*j) * XS_STRIDE + k);

        #pragma unroll
        for (int kkk = 0; kkk < 4; kkk++) {
            unsigned long long bp[4];
            #pragma unroll
            for (int jp = 0; jp < 4; jp++) {
                float blo = ((const float*)&b4[2*jp])[kkk];
                float bhi = ((const float*)&b4[2*jp+1])[kkk];
                bp[jp] = pack2(blo, bhi);
            }
            #pragma unroll
            for (int i = 0; i < 8; i++) {
                float av = ((const float*)&a4[i])[kkk];
                unsigned long long ap = pack2(av, av);
                #pragma unroll
                for (int jp = 0; jp < 4; jp++) fma2(h2[i][jp], ap, bp[jp]);
            }
        }
    }
    __syncthreads();   // done reading W1 before overwriting wh with h

    // epilogue: relu(+b1) -> wh reused as h
    #pragma unroll
    for (int jp = 0; jp < 4; jp++) {
        const int c_lo = tx + 32*jp, c_hi = c_lo + 16;
        const float bl = b1s[c_lo], bh = b1s[c_hi];
        #pragma unroll
        for (int i = 0; i < 8; i++) {
            float2 v = unpack2(h2[i][jp]);
            float vl = v.x + bl; vl = vl > 0.f ? vl : 0.f;
            float vh = v.y + bh; vh = vh > 0.f ? vh : 0.f;
            const int row = ty + 16*i;
            wh[row * XS_STRIDE + c_lo] = vl;
            wh[row * XS_STRIDE + c_hi] = vh;
        }
    }
    __syncthreads();

    // ---- logits: [128 nodes][16], float4 along j ----
    {
        const int n  = tid & 127;
        const int kg = tid >> 7;   // 0 or 1 -> k base 0 / 8
        float lacc[8];
        #pragma unroll
        for (int kk = 0; kk < 8; kk++) lacc[kk] = b2s[kg*8 + kk];
        #pragma unroll 2
        for (int j = 0; j < Cc; j += 4) {
            float4 hv = *(const float4*)(wh + n * XS_STRIDE + j);
            #pragma unroll
            for (int kk = 0; kk < 8; kk++) {
                float4 w = *(const float4*)(w2s + (kg*8 + kk) * Cc + j);
                lacc[kk] += hv.x*w.x + hv.y*w.y + hv.z*w.z + hv.w*w.w;
            }
        }
        #pragma unroll
        for (int kk = 0; kk < 8; kk++)
            larr[n*17 + kg*8 + kk] = lacc[kk] * sc;
    }
    __syncthreads();

    // ---- gumbel softmax + entropy + s output ----
    if (tid < TILE) {
        const int n = tid;
        float gv[16];
        const float4* gp = (const float4*)(gumbel + (size_t)(base + n) * Kk);
        #pragma unroll
        for (int q = 0; q < 4; q++) {
            float4 g = gp[q];
            gv[q*4+0]=g.x; gv[q*4+1]=g.y; gv[q*4+2]=g.z; gv[q*4+3]=g.w;
        }
        float z[16];
        float mx = -3.4e38f;
        #pragma unroll
        for (int k = 0; k < Kk; k++) {
            float l = larr[n*17 + k];
            if (msk[k] == 0.f) l = -1e9f;
            z[k] = l + gv[k];            // TAU = 1.0
            mx = fmaxf(mx, z[k]);
        }
        float sum = 0.f;
        #pragma unroll
        for (int k = 0; k < Kk; k++) { z[k] = __expf(z[k] - mx); sum += z[k]; }
        float inv = 1.f / sum;
        float ent = 0.f;
        float so[16];
        #pragma unroll
        for (int k = 0; k < Kk; k++) {
            float sv = z[k] * inv;
            ss[n*17 + k] = sv;
            so[k] = sv;
            ent += sv * __logf(sv + EPSF);
        }
        float4* sp = (float4*)(s_out + (size_t)(base + n) * Kk);
        #pragma unroll
        for (int q = 0; q < 4; q++)
            sp[q] = make_float4(so[q*4], so[q*4+1], so[q*4+2], so[q*4+3]);
        atomicAdd(entacc, ent);
    }
    __syncthreads();
    if (tid == 0) atomicAdd(&g_ent, entacc[0]);

    // ---- pooling: kk in lane-varying slot -> x reads are warp-broadcast ----
    {
        const int b_lo = bval[0], b_hi = bval[TILE-1];
        const int kk = tid & 15;        // varies across lanes
        const int cg = tid >> 4;        // 0..15 -> c = cg*8 .. cg*8+7
        for (int b = b_lo; b <= b_hi; ++b) {
            unsigned long long acc2[4];
            #pragma unroll
            for (int q = 0; q < 4; q++) acc2[q] = 0ull;
            float ssum = 0.f, p0 = 0.f, p1 = 0.f;
            #pragma unroll 4
            for (int n = 0; n < TILE; n++) {
                if (bval[n] == b) {
                    float sv = ss[n*17 + kk];
                    unsigned long long sp2 = pack2(sv, sv);
                    ulonglong2 xa = *(const ulonglong2*)(xs + n * XS_STRIDE + cg*8);
                    ulonglong2 xb = *(const ulonglong2*)(xs + n * XS_STRIDE + cg*8 + 4);
                    fma2(acc2[0], sp2, xa.x);
                    fma2(acc2[1], sp2, xa.y);
                    fma2(acc2[2], sp2, xb.x);
                    fma2(acc2[3], sp2, xb.y);
                    if (cg == 0) {
                        ssum += sv;
                        p0 += sv * psm[n*2];
                        p1 += sv * psm[n*2+1];
                    }
                }
            }
            float* op = out_pool + ((size_t)(b*Kk + kk)) * Cc + cg*8;
            #pragma unroll
            for (int q = 0; q < 4; q++) {
                float2 v = unpack2(acc2[q]);
                atomicAdd(op + 2*q,     v.x);
                atomicAdd(op + 2*q + 1, v.y);
            }
            if (cg == 0) {
                atomicAdd(&g_sum_s[b*Kk + kk], ssum);
                atomicAdd(&g_sum_pos[(b*Kk + kk)*2],     p0);
                atomicAdd(&g_sum_pos[(b*Kk + kk)*2 + 1], p1);
            }
        }
    }
}

// ---------------- finalize ----------------
__global__ void finalize_kernel(const float* __restrict__ amask,
                                float* __restrict__ out)
{
    __shared__ float avg[Kk];
    __shared__ float mu_s[Bg*Kk*2];
    __shared__ float sepacc;
    const int tid = threadIdx.x;
    if (tid == 0) sepacc = 0.f;
    if (tid < Kk) {
        float s = 0.f;
        for (int b = 0; b < Bg; b++) s += g_sum_s[b*Kk + tid];
        avg[tid] = s / (float)Nn;
    }
    for (int i = tid; i < Bg*Kk*2; i += blockDim.x) {
        int bk = i >> 1;
        float m = g_sum_pos[i] / (g_sum_s[bk] + EPSF);
        mu_s[i] = m;
        out[MU_OFF + i] = m;
    }
    __syncthreads();

    // separation: sum over b of off-diagonal 1/(d^2+1), / (K*(K-1))
    float rep = 0.f;
    for (int i = tid; i < Bg*Kk*Kk; i += blockDim.x) {
        int b = i >> 8, r = i & 255, j = r >> 4, k = r & 15;
        if (j != k) {
            float dx = mu_s[(b*Kk + j)*2]     - mu_s[(b*Kk + k)*2];
            float dy = mu_s[(b*Kk + j)*2 + 1] - mu_s[(b*Kk + k)*2 + 1];
            rep += 1.f / (dx*dx + dy*dy + 1.f);
        }
    }
    #pragma unroll
    for (int off = 16; off; off >>= 1) rep += __shfl_down_sync(0xffffffffu, rep, off);
    if ((tid & 31) == 0) atomicAdd(&sepacc, rep);
    __syncthreads();

    if (tid == 0) {
        const float up = 1.f / (float)Kk;
        float entropy = -g_ent / (float)Nn;
        float div = 0.f, prun = 0.f, msum = 0.f, col = 0.f, mean = 0.f;
        for (int k = 0; k < Kk; k++) {
            div  += up * logf(up / (avg[k] + EPSF));
            prun += fabsf(avg[k] * (1.f - amask[k]));
            msum += amask[k];
            float d = avg[k] - up;
            col  += d * d;
            mean += avg[k];
        }
        prun /= (float)Kk;
        float sparsity = (msum / (float)Kk) * 0.01f;
        col *= 2.0f;
        mean /= (float)Kk;
        float var = 0.f;
        for (int k = 0; k < Kk; k++) { float d = avg[k] - mean; var += d * d; }
        var /= (float)Kk;
        float bal = sqrtf(var);
        float sep = sepacc / (float)(Kk * (Kk - 1));
        float* L = out + LOSS_OFF;
        L[0] = entropy; L[1] = div; L[2] = 0.f; L[3] = prun; L[4] = sparsity;
        L[5] = 0.f;     L[6] = col; L[7] = bal; L[8] = sep;
    }
}

extern "C" void kernel_launch(void* const* d_in, const int* in_sizes, int n_in,
                              void* d_out, int out_size)
{
    const float* x     = (const float*)d_in[0];
    const int*   batch = (const int*)d_in[1];
    const float* pos   = (const float*)d_in[2];
    const float* gum   = (const float*)d_in[3];
    const float* W1    = (const float*)d_in[4];
    const float* b1    = (const float*)d_in[5];
    const float* W2    = (const float*)d_in[6];
    const float* b2    = (const float*)d_in[7];
    const float* scal  = (const float*)d_in[8];
    const float* amask = (const float*)d_in[9];
    float* out = (float*)d_out;

    cudaFuncSetAttribute(fused_kernel,
                         cudaFuncAttributeMaxDynamicSharedMemorySize, SMEM_BYTES);

    init_kernel<<<(Bg*Kk*Cc + NTHREADS - 1)/NTHREADS, NTHREADS>>>(out + OUT_POOL_OFF);
    fused_kernel<<<Nn / TILE, NTHREADS, SMEM_BYTES>>>(
        x, batch, pos, gum, W1, b1, W2, b2, scal, amask,
        out + OUT_POOL_OFF, out + S_OFF);
    finalize_kernel<<<1, NTHREADS>>>(amask, out);
}

// round 5
// speedup vs baseline: 1.3099x; 1.3099x over previous
#include <cuda_runtime.h>
#include <cuda_bf16.h>
#include <math.h>
#include <stdint.h>

#define Nn 131072
#define Bg 16
#define Cc 128
#define Kk 16
#define TILE 128
#define NTHREADS 256
#define EPSF 1e-9f

// d_out layout: out[B,K,C], s[N,K], mu[B,K,2], losses[9]
#define OUT_POOL_OFF 0
#define S_OFF        (Bg*Kk*Cc)
#define MU_OFF       (S_OFF + Nn*Kk)
#define LOSS_OFF     (MU_OFF + Bg*Kk*2)

// ---- smem byte offsets ----
// A/B bf16 operand tiles: 128 rows x 128 bf16, row stride 272B (136 b16) -> conflict-free ldmatrix
#define OPST 272
#define OPBYTES (128*OPST)        // 34816
#define SM_AHI  0
#define SM_ALO  (SM_AHI + OPBYTES)          // 34816
#define SM_BHI  (SM_ALO + OPBYTES)          // 69632
#define SM_BLO  (SM_BHI + OPBYTES)          // 104448  (B region ends 139264)
#define SM_W2   139264                       // f32[16*128]   -> 147456
#define SM_LARR 147456                       // f32[128*17]   -> 156160
#define SM_SS   156160                       // f32[128*17]   -> 164864
#define SM_PSM  164864                       // f32[256]      -> 165888
#define SM_B1   165888                       // f32[128]      -> 166400
#define SM_B2   166400                       // f32[16]
#define SM_MSK  166464                       // f32[16]
#define SM_BVAL 166528                       // int[128]
#define SM_ENT  167040                       // f32[1]
#define SMEM_BYTES 167168
// overlays on the (dead-after-GEMM) B region: h f32[128][132], then xs f32[128][132]
#define SM_H    SM_BHI
#define SM_XS   SM_BHI

// scratch accumulators
__device__ float g_sum_s[Bg*Kk];
__device__ float g_sum_pos[Bg*Kk*2];
__device__ float g_ent;

// ---------------- helpers ----------------
__device__ __forceinline__ uint32_t smem_u32(const void* p) {
    uint32_t a;
    asm("{ .reg .u64 t; cvta.to.shared.u64 t, %1; cvt.u32.u64 %0, t; }"
        : "=r"(a) : "l"(p));
    return a;
}
__device__ __forceinline__ void ldsm_x4(uint32_t* r, uint32_t addr) {
    asm volatile("ldmatrix.sync.aligned.m8n8.x4.shared.b16 {%0,%1,%2,%3}, [%4];"
                 : "=r"(r[0]), "=r"(r[1]), "=r"(r[2]), "=r"(r[3]) : "r"(addr));
}
__device__ __forceinline__ void mma16816(float* c, const uint32_t* a,
                                         uint32_t b0, uint32_t b1) {
    asm volatile("mma.sync.aligned.m16n8k16.row.col.f32.bf16.bf16.f32 "
        "{%0,%1,%2,%3}, {%4,%5,%6,%7}, {%8,%9}, {%0,%1,%2,%3};"
        : "+f"(c[0]), "+f"(c[1]), "+f"(c[2]), "+f"(c[3])
        : "r"(a[0]), "r"(a[1]), "r"(a[2]), "r"(a[3]), "r"(b0), "r"(b1));
}
// split f32 pair into bf16 hi/lo packed words, store at byte offset
__device__ __forceinline__ void cvt_store2(char* hi_b, char* lo_b, int off,
                                           float f0, float f1) {
    __nv_bfloat16 h0 = __float2bfloat16(f0);
    __nv_bfloat16 h1 = __float2bfloat16(f1);
    __nv_bfloat16 l0 = __float2bfloat16(f0 - __bfloat162float(h0));
    __nv_bfloat16 l1 = __float2bfloat16(f1 - __bfloat162float(h1));
    uint32_t hp = (uint32_t)__bfloat16_as_ushort(h0) | ((uint32_t)__bfloat16_as_ushort(h1) << 16);
    uint32_t lp = (uint32_t)__bfloat16_as_ushort(l0) | ((uint32_t)__bfloat16_as_ushort(l1) << 16);
    *(uint32_t*)(hi_b + off) = hp;
    *(uint32_t*)(lo_b + off) = lp;
}

// ---------------- init ----------------
__global__ void init_kernel(float* __restrict__ out_pool) {
    int idx = blockIdx.x * blockDim.x + threadIdx.x;
    if (idx < Bg*Kk*Cc) out_pool[idx] = 0.f;
    if (blockIdx.x == 0) {
        int t = threadIdx.x;
        if (t < Bg*Kk) g_sum_s[t] = 0.f;
        for (int i = t; i < Bg*Kk*2; i += blockDim.x) g_sum_pos[i] = 0.f;
        if (t == 0) g_ent = 0.f;
    }
}

// ---------------- fused main ----------------
extern "C" __global__ void __launch_bounds__(NTHREADS, 1)
fused_kernel(const float* __restrict__ x,
             const int* __restrict__ batch,
             const float* __restrict__ pos,
             const float* __restrict__ gumbel,
             const float* __restrict__ W1,
             const float* __restrict__ b1,
             const float* __restrict__ W2,
             const float* __restrict__ b2,
             const float* __restrict__ scaling_p,
             const float* __restrict__ amask,
             float* __restrict__ out_pool,
             float* __restrict__ s_out)
{
    extern __shared__ char smc[];
    float* w2s  = (float*)(smc + SM_W2);
    float* larr = (float*)(smc + SM_LARR);
    float* ss   = (float*)(smc + SM_SS);
    float* psm  = (float*)(smc + SM_PSM);
    float* b1s  = (float*)(smc + SM_B1);
    float* b2s  = (float*)(smc + SM_B2);
    float* msk  = (float*)(smc + SM_MSK);
    int*   bval = (int*)(smc + SM_BVAL);
    float* entacc = (float*)(smc + SM_ENT);
    float* h_s  = (float*)(smc + SM_H);      // f32[128][132] overlay (post-GEMM)
    float* xs   = (float*)(smc + SM_XS);     // f32[128][132] overlay (post-logits)

    const int tid  = threadIdx.x;
    const int base = blockIdx.x * TILE;
    const int wid = tid >> 5, lane = tid & 31;
    const float sc = __ldg(scaling_p);
    const uint32_t sbase = smem_u32(smc);

    // ---- loads + bf16 hi/lo conversion ----
    for (int r = wid; r < TILE; r += 8) {
        float4 v = ((const float4*)(x + (size_t)(base + r) * Cc))[lane];
        int off = r * OPST + lane * 8;
        cvt_store2(smc + SM_AHI, smc + SM_ALO, off,     v.x, v.y);
        cvt_store2(smc + SM_AHI, smc + SM_ALO, off + 4, v.z, v.w);
    }
    for (int r = wid; r < Cc; r += 8) {
        float4 v = ((const float4*)(W1 + (size_t)r * Cc))[lane];
        int off = r * OPST + lane * 8;
        cvt_store2(smc + SM_BHI, smc + SM_BLO, off,     v.x, v.y);
        cvt_store2(smc + SM_BHI, smc + SM_BLO, off + 4, v.z, v.w);
    }
    for (int r = wid; r < Kk; r += 8) {
        float4 v = ((const float4*)(W2 + (size_t)r * Cc))[lane];
        *(float4*)(w2s + r * Cc + lane * 4) = v;
    }
    if (tid < Cc) b1s[tid] = b1[tid];
    if (tid < Kk) { b2s[tid] = b2[tid]; msk[tid] = amask[tid]; }
    if (tid < TILE) {
        int bv = batch[base + tid];
        bval[tid] = bv < 0 ? 0 : (bv >= Bg ? Bg - 1 : bv);
        psm[tid*2]   = pos[(size_t)(base + tid)*2];
        psm[tid*2+1] = pos[(size_t)(base + tid)*2 + 1];
    }
    if (tid == 0) entacc[0] = 0.f;
    __syncthreads();

    // ---- GEMM1 via HMMA: warp (wm,wn) computes m32 x n64, k=128 ----
    const int wm = wid & 3, wn = wid >> 2;
    float c[2][8][4];
    #pragma unroll
    for (int i = 0; i < 2; i++)
        #pragma unroll
        for (int nb = 0; nb < 8; nb++)
            #pragma unroll
            for (int q = 0; q < 4; q++) c[i][nb][q] = 0.f;

    const uint32_t a_base = sbase + SM_AHI
        + (uint32_t)((wm*32 + (lane & 15)) * OPST + (lane >> 4) * 16);
    const uint32_t b_base = sbase + SM_BHI
        + (uint32_t)((wn*64 + (lane & 7) + ((lane >> 4) & 1)*8) * OPST
                     + ((lane >> 3) & 1) * 16);

    #pragma unroll 2
    for (int ks = 0; ks < 8; ks++) {
        const uint32_t koff = ks * 32;   // 16 bf16 = 32 bytes per k-step
        uint32_t ah[2][4], al[2][4];
        #pragma unroll
        for (int i = 0; i < 2; i++) {
            ldsm_x4(ah[i], a_base + i*(16*OPST) + koff);
            ldsm_x4(al[i], a_base + OPBYTES + i*(16*OPST) + koff);
        }
        #pragma unroll
        for (int jj = 0; jj < 4; jj++) {
            uint32_t bh[4], bl[4];
            ldsm_x4(bh, b_base + jj*(16*OPST) + koff);
            ldsm_x4(bl, b_base + OPBYTES + jj*(16*OPST) + koff);
            #pragma unroll
            for (int i = 0; i < 2; i++) {
                mma16816(c[i][2*jj],   ah[i], bh[0], bh[1]);
                mma16816(c[i][2*jj],   ah[i], bl[0], bl[1]);
                mma16816(c[i][2*jj],   al[i], bh[0], bh[1]);
                mma16816(c[i][2*jj+1], ah[i], bh[2], bh[3]);
                mma16816(c[i][2*jj+1], ah[i], bl[2], bl[3]);
                mma16816(c[i][2*jj+1], al[i], bh[2], bh[3]);
            }
        }
    }
    __syncthreads();   // all warps done reading B region before h overlay

    // ---- epilogue: +b1, relu -> h_s (overlay on B region) ----
    {
        const int qr = lane >> 2, qc = (lane & 3) * 2;
        #pragma unroll
        for (int i = 0; i < 2; i++) {
            const int row0 = wm*32 + i*16 + qr;
            #pragma unroll
            for (int nb = 0; nb < 8; nb++) {
                const int col = wn*64 + nb*8 + qc;
                const float bc0 = b1s[col], bc1 = b1s[col+1];
                float v0 = c[i][nb][0] + bc0, v1 = c[i][nb][1] + bc1;
                float v2 = c[i][nb][2] + bc0, v3 = c[i][nb][3] + bc1;
                float2 p0 = make_float2(v0 > 0.f ? v0 : 0.f, v1 > 0.f ? v1 : 0.f);
                float2 p1 = make_float2(v2 > 0.f ? v2 : 0.f, v3 > 0.f ? v3 : 0.f);
                *(float2*)(h_s + row0 * 132 + col)       = p0;
                *(float2*)(h_s + (row0+8) * 132 + col)   = p1;
            }
        }
    }
    __syncthreads();

    // ---- logits: [128 nodes][16] ----
    {
        const int n  = tid & 127;
        const int kg = tid >> 7;
        float lacc[8];
        #pragma unroll
        for (int kk = 0; kk < 8; kk++) lacc[kk] = b2s[kg*8 + kk];
        #pragma unroll 2
        for (int j = 0; j < Cc; j += 4) {
            float4 hv = *(const float4*)(h_s + n * 132 + j);
            #pragma unroll
            for (int kk = 0; kk < 8; kk++) {
                float4 w = *(const float4*)(w2s + (kg*8 + kk) * Cc + j);
                lacc[kk] += hv.x*w.x + hv.y*w.y + hv.z*w.z + hv.w*w.w;
            }
        }
        #pragma unroll
        for (int kk = 0; kk < 8; kk++)
            larr[n*17 + kg*8 + kk] = lacc[kk] * sc;
    }
    __syncthreads();

    // ---- rebuild xs f32 = hi + lo (overlay over h; h is dead) ----
    for (int idx = tid; idx < 128*32; idx += NTHREADS) {
        const int r = idx >> 5, cq = idx & 31;      // cols 4cq..4cq+3
        const int off = r * OPST + cq * 8;
        __nv_bfloat162 h01 = *(__nv_bfloat162*)(smc + SM_AHI + off);
        __nv_bfloat162 h23 = *(__nv_bfloat162*)(smc + SM_AHI + off + 4);
        __nv_bfloat162 l01 = *(__nv_bfloat162*)(smc + SM_ALO + off);
        __nv_bfloat162 l23 = *(__nv_bfloat162*)(smc + SM_ALO + off + 4);
        float2 hf01 = __bfloat1622float2(h01), hf23 = __bfloat1622float2(h23);
        float2 lf01 = __bfloat1622float2(l01), lf23 = __bfloat1622float2(l23);
        *(float4*)(xs + r * 132 + cq * 4) =
            make_float4(hf01.x + lf01.x, hf01.y + lf01.y,
                        hf23.x + lf23.x, hf23.y + lf23.y);
    }
    __syncthreads();

    // ---- gumbel softmax + entropy + s output ----
    if (tid < TILE) {
        const int n = tid;
        float gv[16];
        const float4* gp = (const float4*)(gumbel + (size_t)(base + n) * Kk);
        #pragma unroll
        for (int q = 0; q < 4; q++) {
            float4 g = gp[q];
            gv[q*4+0]=g.x; gv[q*4+1]=g.y; gv[q*4+2]=g.z; gv[q*4+3]=g.w;
        }
        float z[16];
        float mx = -3.4e38f;
        #pragma unroll
        for (int k = 0; k < Kk; k++) {
            float l = larr[n*17 + k];
            if (msk[k] == 0.f) l = -1e9f;
            z[k] = l + gv[k];
            mx = fmaxf(mx, z[k]);
        }
        float sum = 0.f;
        #pragma unroll
        for (int k = 0; k < Kk; k++) { z[k] = __expf(z[k] - mx); sum += z[k]; }
        float inv = 1.f / sum;
        float ent = 0.f;
        float so[16];
        #pragma unroll
        for (int k = 0; k < Kk; k++) {
            float sv = z[k] * inv;
            ss[n*17 + k] = sv;
            so[k] = sv;
            ent += sv * __logf(sv + EPSF);
        }
        float4* sp = (float4*)(s_out + (size_t)(base + n) * Kk);
        #pragma unroll
        for (int q = 0; q < 4; q++)
            sp[q] = make_float4(so[q*4], so[q*4+1], so[q*4+2], so[q*4+3]);
        atomicAdd(entacc, ent);
    }
    __syncthreads();
    if (tid == 0) atomicAdd(&g_ent, entacc[0]);

    // ---- pooling (batch sorted -> contiguous segments) ----
    {
        const int b_lo = bval[0], b_hi = bval[TILE-1];
        const int kk = tid >> 4;
        const int c0 = tid & 15;
        for (int b = b_lo; b <= b_hi; ++b) {
            float racc[8];
            #pragma unroll
            for (int q = 0; q < 8; q++) racc[q] = 0.f;
            float ssum = 0.f, p0 = 0.f, p1 = 0.f;
            for (int n = 0; n < TILE; n++) {
                if (bval[n] == b) {
                    float sv = ss[n*17 + kk];
                    #pragma unroll
                    for (int q = 0; q < 8; q++)
                        racc[q] += sv * xs[n * 132 + c0 + 16*q];
                    if (c0 == 0) {
                        ssum += sv;
                        p0 += sv * psm[n*2];
                        p1 += sv * psm[n*2+1];
                    }
                }
            }
            float* op = out_pool + ((size_t)(b*Kk + kk)) * Cc;
            #pragma unroll
            for (int q = 0; q < 8; q++) atomicAdd(op + c0 + 16*q, racc[q]);
            if (c0 == 0) {
                atomicAdd(&g_sum_s[b*Kk + kk], ssum);
                atomicAdd(&g_sum_pos[(b*Kk + kk)*2],     p0);
                atomicAdd(&g_sum_pos[(b*Kk + kk)*2 + 1], p1);
            }
        }
    }
}

// ---------------- finalize ----------------
__global__ void finalize_kernel(const float* __restrict__ amask,
                                float* __restrict__ out)
{
    __shared__ float avg[Kk];
    __shared__ float mu_s[Bg*Kk*2];
    __shared__ float sepacc;
    const int tid = threadIdx.x;
    if (tid == 0) sepacc = 0.f;
    if (tid < Kk) {
        float s = 0.f;
        for (int b = 0; b < Bg; b++) s += g_sum_s[b*Kk + tid];
        avg[tid] = s / (float)Nn;
    }
    for (int i = tid; i < Bg*Kk*2; i += blockDim.x) {
        int bk = i >> 1;
        float m = g_sum_pos[i] / (g_sum_s[bk] + EPSF);
        mu_s[i] = m;
        out[MU_OFF + i] = m;
    }
    __syncthreads();

    float rep = 0.f;
    for (int i = tid; i < Bg*Kk*Kk; i += blockDim.x) {
        int b = i >> 8, r = i & 255, j = r >> 4, k = r & 15;
        if (j != k) {
            float dx = mu_s[(b*Kk + j)*2]     - mu_s[(b*Kk + k)*2];
            float dy = mu_s[(b*Kk + j)*2 + 1] - mu_s[(b*Kk + k)*2 + 1];
            rep += 1.f / (dx*dx + dy*dy + 1.f);
        }
    }
    #pragma unroll
    for (int off = 16; off; off >>= 1) rep += __shfl_down_sync(0xffffffffu, rep, off);
    if ((tid & 31) == 0) atomicAdd(&sepacc, rep);
    __syncthreads();

    if (tid == 0) {
        const float up = 1.f / (float)Kk;
        float entropy = -g_ent / (float)Nn;
        float div = 0.f, prun = 0.f, msum = 0.f, col = 0.f, mean = 0.f;
        for (int k = 0; k < Kk; k++) {
            div  += up * logf(up / (avg[k] + EPSF));
            prun += fabsf(avg[k] * (1.f - amask[k]));
            msum += amask[k];
            float d = avg[k] - up;
            col  += d * d;
            mean += avg[k];
        }
        prun /= (float)Kk;
        float sparsity = (msum / (float)Kk) * 0.01f;
        col *= 2.0f;
        mean /= (float)Kk;
        float var = 0.f;
        for (int k = 0; k < Kk; k++) { float d = avg[k] - mean; var += d * d; }
        var /= (float)Kk;
        float bal = sqrtf(var);
        float sep = sepacc / (float)(Kk * (Kk - 1));
        float* L = out + LOSS_OFF;
        L[0] = entropy; L[1] = div; L[2] = 0.f; L[3] = prun; L[4] = sparsity;
        L[5] = 0.f;     L[6] = col; L[7] = bal; L[8] = sep;
    }
}

extern "C" void kernel_launch(void* const* d_in, const int* in_sizes, int n_in,
                              void* d_out, int out_size)
{
    const float* x     = (const float*)d_in[0];
    const int*   batch = (const int*)d_in[1];
    const float* pos   = (const float*)d_in[2];
    const float* gum   = (const float*)d_in[3];
    const float* W1    = (const float*)d_in[4];
    const float* b1    = (const float*)d_in[5];
    const float* W2    = (const float*)d_in[6];
    const float* b2    = (const float*)d_in[7];
    const float* scal  = (const float*)d_in[8];
    const float* amask = (const float*)d_in[9];
    float* out = (float*)d_out;

    cudaFuncSetAttribute(fused_kernel,
                         cudaFuncAttributeMaxDynamicSharedMemorySize, SMEM_BYTES);

    init_kernel<<<(Bg*Kk*Cc + NTHREADS - 1)/NTHREADS, NTHREADS>>>(out + OUT_POOL_OFF);
    fused_kernel<<<Nn / TILE, NTHREADS, SMEM_BYTES>>>(
        x, batch, pos, gum, W1, b1, W2, b2, scal, amask,
        out + OUT_POOL_OFF, out + S_OFF);
    finalize_kernel<<<1, NTHREADS>>>(amask, out);
}

// round 6
// speedup vs baseline: 1.5138x; 1.1557x over previous
#include <cuda_runtime.h>
#include <cuda_bf16.h>
#include <math.h>
#include <stdint.h>

#define Nn 131072
#define Bg 16
#define Cc 128
#define Kk 16
#define TILE 128
#define EPSF 1e-9f

// d_out layout: out[B,K,C], s[N,K], mu[B,K,2], losses[9]
#define OUT_POOL_OFF 0
#define S_OFF        (Bg*Kk*Cc)
#define MU_OFF       (S_OFF + Nn*Kk)
#define LOSS_OFF     (MU_OFF + Bg*Kk*2)

// ---- K1 (mlp) smem: operand tiles 128x128 bf16, row stride 272B ----
#define OPST 272
#define OPBYTES (128*OPST)                  // 34816
#define SM_AHI  0
#define SM_ALO  (SM_AHI + OPBYTES)
#define SM_BHI  (SM_ALO + OPBYTES)
#define SM_BLO  (SM_BHI + OPBYTES)
#define SM_W2   (SM_BLO + OPBYTES)          // 139264, f32[16*128]
#define SM_LARR (SM_W2 + Kk*Cc*4)           // 147456, f32[128*17]
#define SM_B1   (SM_LARR + TILE*17*4)       // 156160
#define SM_B2   (SM_B1 + 512)
#define SM_MSK  (SM_B2 + 64)
#define SM_ENT  (SM_MSK + 64)
#define SMEM1   (SM_ENT + 128)              // ~157KB
#define SM_H    SM_BHI                      // h f32[128][132] overlay post-GEMM

// ---- K3 (pool) smem ----
#define P_XS   0                            // f32[128][132] = 67584
#define P_SS   (128*132*4)
#define P_PSM  (P_SS + TILE*17*4)           // 76288
#define P_BVAL (P_PSM + 1024)               // 77312
#define SMEM3  (P_BVAL + 512)               // 77824 -> 2 CTAs/SM

// scratch accumulators
__device__ float g_sum_s[Bg*Kk];
__device__ float g_sum_pos[Bg*Kk*2];
__device__ float g_ent;

// ---------------- helpers ----------------
__device__ __forceinline__ uint32_t smem_u32(const void* p) {
    uint32_t a;
    asm("{ .reg .u64 t; cvta.to.shared.u64 t, %1; cvt.u32.u64 %0, t; }"
        : "=r"(a) : "l"(p));
    return a;
}
__device__ __forceinline__ void ldsm_x4(uint32_t* r, uint32_t addr) {
    asm volatile("ldmatrix.sync.aligned.m8n8.x4.shared.b16 {%0,%1,%2,%3}, [%4];"
                 : "=r"(r[0]), "=r"(r[1]), "=r"(r[2]), "=r"(r[3]) : "r"(addr));
}
__device__ __forceinline__ void mma16816(float* c, const uint32_t* a,
                                         uint32_t b0, uint32_t b1) {
    asm volatile("mma.sync.aligned.m16n8k16.row.col.f32.bf16.bf16.f32 "
        "{%0,%1,%2,%3}, {%4,%5,%6,%7}, {%8,%9}, {%0,%1,%2,%3};"
        : "+f"(c[0]), "+f"(c[1]), "+f"(c[2]), "+f"(c[3])
        : "r"(a[0]), "r"(a[1]), "r"(a[2]), "r"(a[3]), "r"(b0), "r"(b1));
}
__device__ __forceinline__ void cvt_store2(char* hi_b, char* lo_b, int off,
                                           float f0, float f1) {
    __nv_bfloat16 h0 = __float2bfloat16(f0);
    __nv_bfloat16 h1 = __float2bfloat16(f1);
    __nv_bfloat16 l0 = __float2bfloat16(f0 - __bfloat162float(h0));
    __nv_bfloat16 l1 = __float2bfloat16(f1 - __bfloat162float(h1));
    uint32_t hp = (uint32_t)__bfloat16_as_ushort(h0) | ((uint32_t)__bfloat16_as_ushort(h1) << 16);
    uint32_t lp = (uint32_t)__bfloat16_as_ushort(l0) | ((uint32_t)__bfloat16_as_ushort(l1) << 16);
    *(uint32_t*)(hi_b + off) = hp;
    *(uint32_t*)(lo_b + off) = lp;
}

// ---------------- init ----------------
__global__ void init_kernel(float* __restrict__ out_pool) {
    int idx = blockIdx.x * blockDim.x + threadIdx.x;
    if (idx < Bg*Kk*Cc) out_pool[idx] = 0.f;
    if (blockIdx.x == 0) {
        int t = threadIdx.x;
        if (t < Bg*Kk) g_sum_s[t] = 0.f;
        for (int i = t; i < Bg*Kk*2; i += blockDim.x) g_sum_pos[i] = 0.f;
        if (t == 0) g_ent = 0.f;
    }
}

// ---------------- K1: MLP + logits + softmax (512 threads) ----------------
extern "C" __global__ void __launch_bounds__(512, 1)
mlp_kernel(const float* __restrict__ x,
           const float* __restrict__ gumbel,
           const float* __restrict__ W1,
           const float* __restrict__ b1,
           const float* __restrict__ W2,
           const float* __restrict__ b2,
           const float* __restrict__ scaling_p,
           const float* __restrict__ amask,
           float* __restrict__ s_out)
{
    extern __shared__ char smc[];
    float* w2s  = (float*)(smc + SM_W2);
    float* larr = (float*)(smc + SM_LARR);
    float* b1s  = (float*)(smc + SM_B1);
    float* b2s  = (float*)(smc + SM_B2);
    float* msk  = (float*)(smc + SM_MSK);
    float* entacc = (float*)(smc + SM_ENT);
    float* h_s  = (float*)(smc + SM_H);     // f32[128][132] overlay

    const int tid  = threadIdx.x;
    const int base = blockIdx.x * TILE;
    const int wid = tid >> 5, lane = tid & 31;
    const float sc = __ldg(scaling_p);
    const uint32_t sbase = smem_u32(smc);

    // ---- loads + bf16 hi/lo conversion (16 warps) ----
    for (int r = wid; r < TILE; r += 16) {
        float4 v = ((const float4*)(x + (size_t)(base + r) * Cc))[lane];
        int off = r * OPST + lane * 8;
        cvt_store2(smc + SM_AHI, smc + SM_ALO, off,     v.x, v.y);
        cvt_store2(smc + SM_AHI, smc + SM_ALO, off + 4, v.z, v.w);
    }
    for (int r = wid; r < Cc; r += 16) {
        float4 v = ((const float4*)(W1 + (size_t)r * Cc))[lane];
        int off = r * OPST + lane * 8;
        cvt_store2(smc + SM_BHI, smc + SM_BLO, off,     v.x, v.y);
        cvt_store2(smc + SM_BHI, smc + SM_BLO, off + 4, v.z, v.w);
    }
    if (wid < Kk) {
        float4 v = ((const float4*)(W2 + (size_t)wid * Cc))[lane];
        *(float4*)(w2s + wid * Cc + lane * 4) = v;
    }
    if (tid < Cc) b1s[tid] = b1[tid];
    if (tid < Kk) { b2s[tid] = b2[tid]; msk[tid] = amask[tid]; }
    if (tid == 0) entacc[0] = 0.f;
    __syncthreads();

    // ---- GEMM1 via HMMA: 4x4 warp grid, each m32 x n32, k=128 ----
    const int wm = wid & 3, wn = wid >> 2;
    float c[2][4][4];
    #pragma unroll
    for (int i = 0; i < 2; i++)
        #pragma unroll
        for (int nb = 0; nb < 4; nb++)
            #pragma unroll
            for (int q = 0; q < 4; q++) c[i][nb][q] = 0.f;

    const uint32_t a_base = sbase + SM_AHI
        + (uint32_t)((wm*32 + (lane & 15)) * OPST + (lane >> 4) * 16);
    const uint32_t b_base = sbase + SM_BHI
        + (uint32_t)((wn*32 + (lane & 7) + ((lane >> 4) & 1)*8) * OPST
                     + ((lane >> 3) & 1) * 16);

    #pragma unroll 2
    for (int ks = 0; ks < 8; ks++) {
        const uint32_t koff = ks * 32;
        uint32_t ah[2][4], al[2][4];
        #pragma unroll
        for (int i = 0; i < 2; i++) {
            ldsm_x4(ah[i], a_base + i*(16*OPST) + koff);
            ldsm_x4(al[i], a_base + OPBYTES + i*(16*OPST) + koff);
        }
        #pragma unroll
        for (int jj = 0; jj < 2; jj++) {
            uint32_t bh[4], bl[4];
            ldsm_x4(bh, b_base + jj*(16*OPST) + koff);
            ldsm_x4(bl, b_base + OPBYTES + jj*(16*OPST) + koff);
            #pragma unroll
            for (int i = 0; i < 2; i++) {
                mma16816(c[i][2*jj],   ah[i], bh[0], bh[1]);
                mma16816(c[i][2*jj],   ah[i], bl[0], bl[1]);
                mma16816(c[i][2*jj],   al[i], bh[0], bh[1]);
                mma16816(c[i][2*jj+1], ah[i], bh[2], bh[3]);
                mma16816(c[i][2*jj+1], ah[i], bl[2], bl[3]);
                mma16816(c[i][2*jj+1], al[i], bh[2], bh[3]);
            }
        }
    }
    __syncthreads();   // all warps done reading B before h overlay

    // ---- epilogue: +b1, relu -> h_s ----
    {
        const int qr = lane >> 2, qc = (lane & 3) * 2;
        #pragma unroll
        for (int i = 0; i < 2; i++) {
            const int row0 = wm*32 + i*16 + qr;
            #pragma unroll
            for (int nb = 0; nb < 4; nb++) {
                const int col = wn*32 + nb*8 + qc;
                const float bc0 = b1s[col], bc1 = b1s[col+1];
                float v0 = c[i][nb][0] + bc0, v1 = c[i][nb][1] + bc1;
                float v2 = c[i][nb][2] + bc0, v3 = c[i][nb][3] + bc1;
                float2 p0 = make_float2(v0 > 0.f ? v0 : 0.f, v1 > 0.f ? v1 : 0.f);
                float2 p1 = make_float2(v2 > 0.f ? v2 : 0.f, v3 > 0.f ? v3 : 0.f);
                *(float2*)(h_s + row0 * 132 + col)     = p0;
                *(float2*)(h_s + (row0+8) * 132 + col) = p1;
            }
        }
    }
    __syncthreads();

    // ---- logits: 512 threads, each (node n, 4 k's) ----
    {
        const int n  = tid & 127;
        const int kg = tid >> 7;   // 0..3 -> k base 4*kg
        float lacc[4];
        #pragma unroll
        for (int kk = 0; kk < 4; kk++) lacc[kk] = b2s[kg*4 + kk];
        #pragma unroll 2
        for (int j = 0; j < Cc; j += 4) {
            float4 hv = *(const float4*)(h_s + n * 132 + j);
            #pragma unroll
            for (int kk = 0; kk < 4; kk++) {
                float4 w = *(const float4*)(w2s + (kg*4 + kk) * Cc + j);
                lacc[kk] += hv.x*w.x + hv.y*w.y + hv.z*w.z + hv.w*w.w;
            }
        }
        #pragma unroll
        for (int kk = 0; kk < 4; kk++)
            larr[n*17 + kg*4 + kk] = lacc[kk] * sc;
    }
    __syncthreads();

    // ---- gumbel softmax + entropy + s output (128 threads) ----
    if (tid < TILE) {
        const int n = tid;
        float gv[16];
        const float4* gp = (const float4*)(gumbel + (size_t)(base + n) * Kk);
        #pragma unroll
        for (int q = 0; q < 4; q++) {
            float4 g = gp[q];
            gv[q*4+0]=g.x; gv[q*4+1]=g.y; gv[q*4+2]=g.z; gv[q*4+3]=g.w;
        }
        float z[16];
        float mx = -3.4e38f;
        #pragma unroll
        for (int k = 0; k < Kk; k++) {
            float l = larr[n*17 + k];
            if (msk[k] == 0.f) l = -1e9f;
            z[k] = l + gv[k];
            mx = fmaxf(mx, z[k]);
        }
        float sum = 0.f;
        #pragma unroll
        for (int k = 0; k < Kk; k++) { z[k] = __expf(z[k] - mx); sum += z[k]; }
        float inv = 1.f / sum;
        float ent = 0.f;
        float so[16];
        #pragma unroll
        for (int k = 0; k < Kk; k++) {
            float sv = z[k] * inv;
            so[k] = sv;
            ent += sv * __logf(sv + EPSF);
        }
        float4* sp = (float4*)(s_out + (size_t)(base + n) * Kk);
        #pragma unroll
        for (int q = 0; q < 4; q++)
            sp[q] = make_float4(so[q*4], so[q*4+1], so[q*4+2], so[q*4+3]);
        atomicAdd(entacc, ent);
    }
    __syncthreads();
    if (tid == 0) atomicAdd(&g_ent, entacc[0]);
}

// ---------------- K3: pooling (256 threads, 2 CTAs/SM) ----------------
extern "C" __global__ void __launch_bounds__(256, 2)
pool_kernel(const float* __restrict__ x,
            const int* __restrict__ batch,
            const float* __restrict__ pos,
            const float* __restrict__ s_in,
            float* __restrict__ out_pool)
{
    extern __shared__ char smc[];
    float* xs   = (float*)(smc + P_XS);    // [128][132]
    float* ss   = (float*)(smc + P_SS);    // [128][17]
    float* psm  = (float*)(smc + P_PSM);
    int*   bval = (int*)(smc + P_BVAL);

    const int tid  = threadIdx.x;
    const int base = blockIdx.x * TILE;
    const int wid = tid >> 5, lane = tid & 31;

    for (int r = wid; r < TILE; r += 8) {
        float4 v = ((const float4*)(x + (size_t)(base + r) * Cc))[lane];
        *(float4*)(xs + r * 132 + lane * 4) = v;
    }
    for (int idx = tid; idx < TILE*4; idx += 256) {
        const int r = idx >> 2, q = idx & 3;
        float4 v = ((const float4*)(s_in + (size_t)(base + r) * Kk))[q];
        ss[r*17 + q*4 + 0] = v.x;  ss[r*17 + q*4 + 1] = v.y;
        ss[r*17 + q*4 + 2] = v.z;  ss[r*17 + q*4 + 3] = v.w;
    }
    if (tid < TILE) {
        int bv = batch[base + tid];
        bval[tid] = bv < 0 ? 0 : (bv >= Bg ? Bg - 1 : bv);
        psm[tid*2]   = pos[(size_t)(base + tid)*2];
        psm[tid*2+1] = pos[(size_t)(base + tid)*2 + 1];
    }
    __syncthreads();

    const int b_lo = bval[0], b_hi = bval[TILE-1];
    const int kk = tid >> 4;
    const int c0 = tid & 15;
    for (int b = b_lo; b <= b_hi; ++b) {
        float racc[8];
        #pragma unroll
        for (int q = 0; q < 8; q++) racc[q] = 0.f;
        float ssum = 0.f, p0 = 0.f, p1 = 0.f;
        for (int n = 0; n < TILE; n++) {
            if (bval[n] == b) {
                float sv = ss[n*17 + kk];
                #pragma unroll
                for (int q = 0; q < 8; q++)
                    racc[q] += sv * xs[n * 132 + c0 + 16*q];
                if (c0 == 0) {
                    ssum += sv;
                    p0 += sv * psm[n*2];
                    p1 += sv * psm[n*2+1];
                }
            }
        }
        float* op = out_pool + ((size_t)(b*Kk + kk)) * Cc;
        #pragma unroll
        for (int q = 0; q < 8; q++) atomicAdd(op + c0 + 16*q, racc[q]);
        if (c0 == 0) {
            atomicAdd(&g_sum_s[b*Kk + kk], ssum);
            atomicAdd(&g_sum_pos[(b*Kk + kk)*2],     p0);
            atomicAdd(&g_sum_pos[(b*Kk + kk)*2 + 1], p1);
        }
    }
}

// ---------------- finalize ----------------
__global__ void finalize_kernel(const float* __restrict__ amask,
                                float* __restrict__ out)
{
    __shared__ float avg[Kk];
    __shared__ float mu_s[Bg*Kk*2];
    __shared__ float sepacc;
    const int tid = threadIdx.x;
    if (tid == 0) sepacc = 0.f;
    if (tid < Kk) {
        float s = 0.f;
        for (int b = 0; b < Bg; b++) s += g_sum_s[b*Kk + tid];
        avg[tid] = s / (float)Nn;
    }
    for (int i = tid; i < Bg*Kk*2; i += blockDim.x) {
        int bk = i >> 1;
        float m = g_sum_pos[i] / (g_sum_s[bk] + EPSF);
        mu_s[i] = m;
        out[MU_OFF + i] = m;
    }
    __syncthreads();

    float rep = 0.f;
    for (int i = tid; i < Bg*Kk*Kk; i += blockDim.x) {
        int b = i >> 8, r = i & 255, j = r >> 4, k = r & 15;
        if (j != k) {
            float dx = mu_s[(b*Kk + j)*2]     - mu_s[(b*Kk + k)*2];
            float dy = mu_s[(b*Kk + j)*2 + 1] - mu_s[(b*Kk + k)*2 + 1];
            rep += 1.f / (dx*dx + dy*dy + 1.f);
        }
    }
    #pragma unroll
    for (int off = 16; off; off >>= 1) rep += __shfl_down_sync(0xffffffffu, rep, off);
    if ((tid & 31) == 0) atomicAdd(&sepacc, rep);
    __syncthreads();

    if (tid == 0) {
        const float up = 1.f / (float)Kk;
        float entropy = -g_ent / (float)Nn;
        float div = 0.f, prun = 0.f, msum = 0.f, col = 0.f, mean = 0.f;
        for (int k = 0; k < Kk; k++) {
            div  += up * logf(up / (avg[k] + EPSF));
            prun += fabsf(avg[k] * (1.f - amask[k]));
            msum += amask[k];
            float d = avg[k] - up;
            col  += d * d;
            mean += avg[k];
        }
        prun /= (float)Kk;
        float sparsity = (msum / (float)Kk) * 0.01f;
        col *= 2.0f;
        mean /= (float)Kk;
        float var = 0.f;
        for (int k = 0; k < Kk; k++) { float d = avg[k] - mean; var += d * d; }
        var /= (float)Kk;
        float bal = sqrtf(var);
        float sep = sepacc / (float)(Kk * (Kk - 1));
        float* L = out + LOSS_OFF;
        L[0] = entropy; L[1] = div; L[2] = 0.f; L[3] = prun; L[4] = sparsity;
        L[5] = 0.f;     L[6] = col; L[7] = bal; L[8] = sep;
    }
}

extern "C" void kernel_launch(void* const* d_in, const int* in_sizes, int n_in,
                              void* d_out, int out_size)
{
    const float* x     = (const float*)d_in[0];
    const int*   batch = (const int*)d_in[1];
    const float* pos   = (const float*)d_in[2];
    const float* gum   = (const float*)d_in[3];
    const float* W1    = (const float*)d_in[4];
    const float* b1    = (const float*)d_in[5];
    const float* W2    = (const float*)d_in[6];
    const float* b2    = (const float*)d_in[7];
    const float* scal  = (const float*)d_in[8];
    const float* amask = (const float*)d_in[9];
    float* out = (float*)d_out;

    cudaFuncSetAttribute(mlp_kernel,
                         cudaFuncAttributeMaxDynamicSharedMemorySize, SMEM1);
    cudaFuncSetAttribute(pool_kernel,
                         cudaFuncAttributeMaxDynamicSharedMemorySize, SMEM3);

    init_kernel<<<(Bg*Kk*Cc + 255)/256, 256>>>(out + OUT_POOL_OFF);
    mlp_kernel<<<Nn / TILE, 512, SMEM1>>>(
        x, gum, W1, b1, W2, b2, scal, amask, out + S_OFF);
    pool_kernel<<<Nn / TILE, 256, SMEM3>>>(
        x, batch, pos, out + S_OFF, out + OUT_POOL_OFF);
    finalize_kernel<<<1, 256>>>(amask, out);
}